// round 16
// baseline (speedup 1.0000x reference)
#include <cuda_runtime.h>
#include <cuda_bf16.h>

#define BATCH     1024
#define CODE_LEN  65536
#define NTHREADS  512
#define NF4       (CODE_LEN / 4)                 /* 16384 float4 per row */
#define DEPTH     8                              /* loads batched per stream */
#define GROUPS    (NF4 / NTHREADS / DEPTH)       /* 4 groups */
#define MARGIN_F  0.01f

// Scratch (device globals; no allocation allowed)
__device__ float g_row_hinged[BATCH];
__device__ unsigned int g_done_count;   // zero-init; reset by last block

__device__ __forceinline__ float4 ldcs4(const float4* p) {
    float4 v;
    asm volatile("ld.global.cs.v4.f32 {%0,%1,%2,%3}, [%4];"
                 : "=f"(v.x), "=f"(v.y), "=f"(v.z), "=f"(v.w)
                 : "l"(p));
    return v;
}

__global__ __launch_bounds__(NTHREADS, 4)   // force <=32 regs -> 4 CTAs/SM
void mse_hinge_fused_kernel(const float* __restrict__ z1,
                            const float* __restrict__ z2,
                            float* __restrict__ out) {
    const int row = blockIdx.x;
    const float4* __restrict__ a =
        reinterpret_cast<const float4*>(z1 + (size_t)row * CODE_LEN);
    const float4* __restrict__ b =
        reinterpret_cast<const float4*>(z2 + (size_t)row * CODE_LEN);

    float acc0 = 0.0f, acc1 = 0.0f;
    for (int g = 0; g < GROUPS; ++g) {
        const int base = threadIdx.x + g * (NTHREADS * DEPTH);

        // Burst-batched: DEPTH stream-a loads, then DEPTH stream-b loads.
        // Loads remain 8KB-strided (measured optimum from the stride sweep).
        float4 va[DEPTH], vb[DEPTH];
        #pragma unroll
        for (int j = 0; j < DEPTH; ++j)
            va[j] = ldcs4(a + base + j * NTHREADS);
        #pragma unroll
        for (int j = 0; j < DEPTH; ++j)
            vb[j] = ldcs4(b + base + j * NTHREADS);

        #pragma unroll
        for (int j = 0; j < DEPTH; ++j) {
            float d0 = va[j].x - vb[j].x;
            float d1 = va[j].y - vb[j].y;
            float d2 = va[j].z - vb[j].z;
            float d3 = va[j].w - vb[j].w;
            acc0 = fmaf(d0, d0, acc0);
            acc1 = fmaf(d1, d1, acc1);
            acc0 = fmaf(d2, d2, acc0);
            acc1 = fmaf(d3, d3, acc1);
        }
    }
    float acc = acc0 + acc1;

    // warp reduce
    #pragma unroll
    for (int o = 16; o > 0; o >>= 1)
        acc += __shfl_xor_sync(0xffffffffu, acc, o);

    __shared__ float s_part[NTHREADS / 32];
    __shared__ bool  s_is_last;
    if ((threadIdx.x & 31) == 0)
        s_part[threadIdx.x >> 5] = acc;
    __syncthreads();

    if (threadIdx.x < 32) {
        float v = (threadIdx.x < NTHREADS / 32) ? s_part[threadIdx.x] : 0.0f;
        #pragma unroll
        for (int o = 8; o > 0; o >>= 1)
            v += __shfl_xor_sync(0xffffffffu, v, o);
        if (threadIdx.x == 0) {
            float mse = v * (1.0f / (float)CODE_LEN);
            g_row_hinged[row] = (mse > MARGIN_F) ? (mse - MARGIN_F) : 0.0f;
            __threadfence();
            unsigned int prev = atomicAdd(&g_done_count, 1u);
            s_is_last = (prev == BATCH - 1);
        }
    }
    __syncthreads();

    // Last-arriving block performs the final deterministic reduction.
    if (s_is_last) {
        if (threadIdx.x == 0)
            g_done_count = 0;   // reset for next graph replay

        float v = g_row_hinged[threadIdx.x] + g_row_hinged[threadIdx.x + NTHREADS];

        #pragma unroll
        for (int o = 16; o > 0; o >>= 1)
            v += __shfl_xor_sync(0xffffffffu, v, o);

        __shared__ float s_fin[NTHREADS / 32];
        if ((threadIdx.x & 31) == 0)
            s_fin[threadIdx.x >> 5] = v;
        __syncthreads();

        if (threadIdx.x < 32) {
            float w = (threadIdx.x < NTHREADS / 32) ? s_fin[threadIdx.x] : 0.0f;
            #pragma unroll
            for (int o = 8; o > 0; o >>= 1)
                w += __shfl_xor_sync(0xffffffffu, w, o);
            if (threadIdx.x == 0)
                out[0] = w * (1.0f / (float)BATCH);
        }
    }
}

extern "C" void kernel_launch(void* const* d_in, const int* in_sizes, int n_in,
                              void* d_out, int out_size) {
    const float* z1 = (const float*)d_in[0];
    const float* z2 = (const float*)d_in[1];
    float* out = (float*)d_out;

    mse_hinge_fused_kernel<<<BATCH, NTHREADS>>>(z1, z2, out);
}